// round 1
// baseline (speedup 1.0000x reference)
#include <cuda_runtime.h>
#include <cstdint>

// ---------------- problem constants ----------------
#define T_TOK   8192
#define DMODEL  1024
#define DFF     4096
#define NEXP    8
#define NSLOTS  (T_TOK * 2)      // top-2 routing: exactly 2*T slots
#define MAXTILES 160             // sum ceil(count_e/128) <= 16384/128 + 8 = 136

// ---------------- device scratch (static; no allocation) ----------------
__device__ float g_h[(size_t)NSLOTS * DFF];     // 256 MiB intermediate (fp32)
__device__ float g_y[(size_t)NSLOTS * DMODEL];  // 64 MiB expert outputs per slot
__device__ int   g_tok[NSLOTS];                 // slot -> token
__device__ int   g_e0[T_TOK], g_e1[T_TOK];
__device__ int   g_s0[T_TOK], g_s1[T_TOK];
__device__ float g_w0[T_TOK], g_w1[T_TOK];
__device__ int   g_counts[NEXP], g_offsets[NEXP], g_fill[NEXP];
__device__ int   g_ntiles;
__device__ int   g_tile_e[MAXTILES], g_tile_start[MAXTILES], g_tile_cnt[MAXTILES];

// ---------------- helpers ----------------
__device__ __forceinline__ float tf32r(float x) {
    uint32_t u;
    asm("cvt.rna.tf32.f32 %0, %1;" : "=r"(u) : "f"(x));
    return __uint_as_float(u);
}

__device__ __forceinline__ void mma_tf32(float* d, const uint32_t* a, const uint32_t* b) {
    asm volatile(
        "mma.sync.aligned.m16n8k8.row.col.f32.tf32.tf32.f32 "
        "{%0,%1,%2,%3}, {%4,%5,%6,%7}, {%8,%9}, {%0,%1,%2,%3};\n"
        : "+f"(d[0]), "+f"(d[1]), "+f"(d[2]), "+f"(d[3])
        : "r"(a[0]), "r"(a[1]), "r"(a[2]), "r"(a[3]),
          "r"(b[0]), "r"(b[1]));
}

// ---------------- kernels ----------------
__global__ void init_kernel() {
    int i = threadIdx.x;
    if (i < NEXP) g_counts[i] = 0;
}

// One warp per token: logits = x@gate_w + gate_b, + gumbel, top-2, softmax(2)
__global__ void gate_kernel(const float* __restrict__ x,
                            const float* __restrict__ gumbel,
                            const float* __restrict__ gw,
                            const float* __restrict__ gb) {
    int t    = (blockIdx.x * blockDim.x + threadIdx.x) >> 5;
    int lane = threadIdx.x & 31;
    if (t >= T_TOK) return;
    const float* xr = x + (size_t)t * DMODEL;
    float acc[NEXP];
#pragma unroll
    for (int e = 0; e < NEXP; e++) acc[e] = 0.f;
    for (int d = lane * 4; d < DMODEL; d += 128) {
        float4 xv = *reinterpret_cast<const float4*>(xr + d);
        float xs[4] = {xv.x, xv.y, xv.z, xv.w};
        const float* g0 = gw + (size_t)d * NEXP;
#pragma unroll
        for (int j = 0; j < 4; j++) {
#pragma unroll
            for (int e = 0; e < NEXP; e++) acc[e] += xs[j] * g0[j * NEXP + e];
        }
    }
#pragma unroll
    for (int e = 0; e < NEXP; e++) {
#pragma unroll
        for (int off = 16; off; off >>= 1)
            acc[e] += __shfl_xor_sync(0xffffffffu, acc[e], off);
    }
    if (lane == 0) {
        float v[NEXP];
#pragma unroll
        for (int e = 0; e < NEXP; e++)
            v[e] = acc[e] + gb[e] + gumbel[t * NEXP + e];
        // top-2, earliest-index tie break (matches jax.lax.top_k)
        int b0 = 0; float m0 = v[0];
#pragma unroll
        for (int e = 1; e < NEXP; e++) { if (v[e] > m0) { m0 = v[e]; b0 = e; } }
        int b1 = -1; float m1 = -3.4e38f;
#pragma unroll
        for (int e = 0; e < NEXP; e++) {
            if (e == b0) continue;
            if (v[e] > m1) { m1 = v[e]; b1 = e; }
        }
        float e1v = expf(m1 - m0);
        float inv = 1.f / (1.f + e1v);
        g_e0[t] = b0; g_e1[t] = b1;
        g_w0[t] = inv; g_w1[t] = e1v * inv;
        atomicAdd(&g_counts[b0], 1);
        atomicAdd(&g_counts[b1], 1);
    }
}

// single thread: exclusive scan + m-tile map
__global__ void scan_kernel() {
    if (blockIdx.x == 0 && threadIdx.x == 0) {
        int off = 0, nt = 0;
        for (int e = 0; e < NEXP; e++) {
            g_offsets[e] = off;
            g_fill[e] = 0;
            int c = g_counts[e];
            for (int s = 0; s < c; s += 128) {
                g_tile_e[nt] = e;
                g_tile_start[nt] = off + s;
                g_tile_cnt[nt] = (c - s < 128) ? (c - s) : 128;
                nt++;
            }
            off += c;
        }
        g_ntiles = nt;
    }
}

__global__ void scatter_kernel() {
    int t = blockIdx.x * blockDim.x + threadIdx.x;
    if (t >= T_TOK) return;
    int e0 = g_e0[t];
    int s0 = g_offsets[e0] + atomicAdd(&g_fill[e0], 1);
    g_tok[s0] = t; g_s0[t] = s0;
    int e1 = g_e1[t];
    int s1 = g_offsets[e1] + atomicAdd(&g_fill[e1], 1);
    g_tok[s1] = t; g_s1[t] = s1;
}

// Grouped GEMM, tf32 mma.sync. BM=128 BN=128 BK=32, 8 warps (warp tile 32x64).
// GATHER: A rows indirected via g_tok (GEMM1, A = x). Otherwise A = g_h rows = slots.
// RELU:   GEMM1 epilogue (+b1, relu, -> g_h). Otherwise +b2 -> g_y.
template <bool GATHER, bool RELU>
__global__ void __launch_bounds__(256)
gemm_kernel(const float* __restrict__ Aext, int lda,
            const float* __restrict__ B, long estride, int ldb,
            const float* __restrict__ bias, int ldo, int Ksize) {
    __shared__ float As[128][33];
    __shared__ float Bs[32][129];

    int bx = blockIdx.x;
    if (bx >= g_ntiles) return;
    int e     = g_tile_e[bx];
    int slot0 = g_tile_start[bx];
    int mc    = g_tile_cnt[bx];
    int n0    = blockIdx.y * 128;

    const float* Abase = GATHER ? Aext : g_h;
    float*       Out   = RELU ? g_h : g_y;
    const float* Be    = B + (size_t)e * estride;
    const float* biasE = bias + (size_t)e * ldo;

    int tid  = threadIdx.x;
    int lane = tid & 31, wid = tid >> 5;
    int warpM = wid & 3, warpN = wid >> 2;   // 4 x 2 warps, 32 x 64 each
    int gid = lane >> 2, tig = lane & 3;

    // A staging pointers: thread covers 4 float4s (rows it*32 + tid/8, cols (tid&7)*4)
    const float* aptr[4];
    int am[4], avalid[4];
#pragma unroll
    for (int it = 0; it < 4; it++) {
        int m = it * 32 + (tid >> 3);
        am[it] = m;
        int val = (m < mc);
        avalid[it] = val;
        int arow = GATHER ? (val ? g_tok[slot0 + m] : 0) : (slot0 + m);
        aptr[it] = Abase + (size_t)arow * lda + (tid & 7) * 4;
    }
    // B staging pointers: thread covers 4 float4s (row fid/32, cols (fid&31)*4)
    const float* bptr[4];
    int bkr[4], bnc[4];
#pragma unroll
    for (int it = 0; it < 4; it++) {
        int fid = it * 256 + tid;
        bkr[it] = fid >> 5;
        bnc[it] = (fid & 31) * 4;
        bptr[it] = Be + (size_t)bkr[it] * ldb + n0 + bnc[it];
    }

    float c[2][8][4];
#pragma unroll
    for (int mt = 0; mt < 2; mt++)
#pragma unroll
        for (int nt = 0; nt < 8; nt++)
#pragma unroll
            for (int q = 0; q < 4; q++) c[mt][nt][q] = 0.f;

    for (int k0 = 0; k0 < Ksize; k0 += 32) {
#pragma unroll
        for (int it = 0; it < 4; it++) {
            float4 v = make_float4(0.f, 0.f, 0.f, 0.f);
            if (avalid[it]) v = *reinterpret_cast<const float4*>(aptr[it] + k0);
            int kc = (tid & 7) * 4;
            As[am[it]][kc + 0] = tf32r(v.x);
            As[am[it]][kc + 1] = tf32r(v.y);
            As[am[it]][kc + 2] = tf32r(v.z);
            As[am[it]][kc + 3] = tf32r(v.w);
        }
#pragma unroll
        for (int it = 0; it < 4; it++) {
            float4 v = *reinterpret_cast<const float4*>(bptr[it] + (size_t)k0 * ldb);
            Bs[bkr[it]][bnc[it] + 0] = tf32r(v.x);
            Bs[bkr[it]][bnc[it] + 1] = tf32r(v.y);
            Bs[bkr[it]][bnc[it] + 2] = tf32r(v.z);
            Bs[bkr[it]][bnc[it] + 3] = tf32r(v.w);
        }
        __syncthreads();
#pragma unroll
        for (int ks = 0; ks < 4; ks++) {
            int kb = ks * 8;
            uint32_t af[2][4];
#pragma unroll
            for (int mt = 0; mt < 2; mt++) {
                int r0 = warpM * 32 + mt * 16 + gid;
                af[mt][0] = __float_as_uint(As[r0][kb + tig]);
                af[mt][1] = __float_as_uint(As[r0 + 8][kb + tig]);
                af[mt][2] = __float_as_uint(As[r0][kb + tig + 4]);
                af[mt][3] = __float_as_uint(As[r0 + 8][kb + tig + 4]);
            }
            uint32_t bf[8][2];
#pragma unroll
            for (int nt = 0; nt < 8; nt++) {
                int c0 = warpN * 64 + nt * 8 + gid;
                bf[nt][0] = __float_as_uint(Bs[kb + tig][c0]);
                bf[nt][1] = __float_as_uint(Bs[kb + tig + 4][c0]);
            }
#pragma unroll
            for (int mt = 0; mt < 2; mt++)
#pragma unroll
                for (int nt = 0; nt < 8; nt++)
                    mma_tf32(c[mt][nt], af[mt], bf[nt]);
        }
        __syncthreads();
    }

    // epilogue: +bias (, relu), write rows slot0+r
#pragma unroll
    for (int mt = 0; mt < 2; mt++) {
        int rb = warpM * 32 + mt * 16 + gid;
#pragma unroll
        for (int half = 0; half < 2; half++) {
            int r = rb + half * 8;
            if (r < mc) {
                float* orow = Out + (size_t)(slot0 + r) * ldo;
#pragma unroll
                for (int nt = 0; nt < 8; nt++) {
                    int nc = n0 + warpN * 64 + nt * 8 + 2 * tig;
                    float v0 = c[mt][nt][half * 2 + 0] + biasE[nc];
                    float v1 = c[mt][nt][half * 2 + 1] + biasE[nc + 1];
                    if (RELU) { v0 = fmaxf(v0, 0.f); v1 = fmaxf(v1, 0.f); }
                    orow[nc]     = v0;
                    orow[nc + 1] = v1;
                }
            }
        }
    }
}

__global__ void combine_kernel(float* __restrict__ out) {
    int idx = blockIdx.x * blockDim.x + threadIdx.x;  // over T * DMODEL/4
    if (idx >= T_TOK * (DMODEL / 4)) return;
    int t = idx / (DMODEL / 4);
    int j = (idx % (DMODEL / 4)) * 4;
    float w0 = g_w0[t], w1 = g_w1[t];
    const float4 a = *reinterpret_cast<const float4*>(&g_y[(size_t)g_s0[t] * DMODEL + j]);
    const float4 b = *reinterpret_cast<const float4*>(&g_y[(size_t)g_s1[t] * DMODEL + j]);
    float4 o;
    o.x = w0 * a.x + w1 * b.x;
    o.y = w0 * a.y + w1 * b.y;
    o.z = w0 * a.z + w1 * b.z;
    o.w = w0 * a.w + w1 * b.w;
    *reinterpret_cast<float4*>(out + (size_t)t * DMODEL + j) = o;
}

// ---------------- launch ----------------
extern "C" void kernel_launch(void* const* d_in, const int* in_sizes, int n_in,
                              void* d_out, int out_size) {
    const float* x      = (const float*)d_in[0];
    const float* gumbel = (const float*)d_in[1];
    const float* gw     = (const float*)d_in[2];
    const float* gb     = (const float*)d_in[3];
    const float* w1     = (const float*)d_in[4];
    const float* b1     = (const float*)d_in[5];
    const float* w2     = (const float*)d_in[6];
    const float* b2     = (const float*)d_in[7];
    float* out = (float*)d_out;

    init_kernel<<<1, 32>>>();
    gate_kernel<<<T_TOK / 8, 256>>>(x, gumbel, gw, gb);
    scan_kernel<<<1, 1>>>();
    scatter_kernel<<<(T_TOK + 255) / 256, 256>>>();
    // GEMM1: h = relu(x[tok] @ w1[e] + b1[e])   (K=DMODEL, N=DFF)
    gemm_kernel<true, true><<<dim3(MAXTILES, DFF / 128), 256>>>(
        x, DMODEL, w1, (long)DMODEL * DFF, DFF, b1, DFF, DMODEL);
    // GEMM2: y = h @ w2[e] + b2[e]              (K=DFF, N=DMODEL)
    gemm_kernel<false, false><<<dim3(MAXTILES, DMODEL / 128), 256>>>(
        nullptr, DFF, w2, (long)DFF * DMODEL, DMODEL, b2, DMODEL, DFF);
    combine_kernel<<<(T_TOK * (DMODEL / 4) + 255) / 256, 256>>>(out);
}

// round 5
// speedup vs baseline: 2.4414x; 2.4414x over previous
#include <cuda_runtime.h>
#include <cstdint>

// ---------------- problem constants ----------------
#define T_TOK   8192
#define DMODEL  1024
#define DFF     4096
#define NEXP    8
#define NSLOTS  (T_TOK * 2)
#define MAXTILES 160

// ---------------- device scratch (static; no allocation) ----------------
__device__ float g_h[(size_t)NSLOTS * DFF];            // 256 MiB (tf32-rounded fp32)
__device__ float g_y[(size_t)NSLOTS * DMODEL];         // 64 MiB
__device__ float g_w1r[(size_t)NEXP * DMODEL * DFF];   // RNA-rounded w1, same layout
__device__ float g_w2r[(size_t)NEXP * DFF * DMODEL];   // RNA-rounded w2, same layout
__device__ float g_xr[(size_t)T_TOK * DMODEL];         // RNA-rounded x
__device__ int   g_tok[NSLOTS];
__device__ int   g_e0[T_TOK], g_e1[T_TOK];
__device__ int   g_s0[T_TOK], g_s1[T_TOK];
__device__ float g_w0[T_TOK], g_w1w[T_TOK];
__device__ int   g_counts[NEXP], g_offsets[NEXP], g_fill[NEXP];
__device__ int   g_ntiles;
__device__ int   g_tile_e[MAXTILES], g_tile_start[MAXTILES], g_tile_cnt[MAXTILES];

// ---------------- helpers ----------------
__device__ __forceinline__ float tf32r(float x) {
    uint32_t u;
    asm("cvt.rna.tf32.f32 %0, %1;" : "=r"(u) : "f"(x));
    return __uint_as_float(u);
}
__device__ __forceinline__ uint32_t smem_u32(const void* p) {
    uint32_t a;
    asm("{ .reg .u64 t; cvta.to.shared.u64 t, %1; cvt.u32.u64 %0, t; }" : "=r"(a) : "l"(p));
    return a;
}
__device__ __forceinline__ void cp16(uint32_t dst, const void* src) {
    asm volatile("cp.async.cg.shared.global [%0], [%1], 16;" :: "r"(dst), "l"(src));
}
__device__ __forceinline__ void cp_commit() {
    asm volatile("cp.async.commit_group;" ::: "memory");
}
__device__ __forceinline__ void cp_wait1() {
    asm volatile("cp.async.wait_group 1;" ::: "memory");
}
__device__ __forceinline__ float lds(uint32_t addr) {
    float v;
    asm volatile("ld.shared.f32 %0, [%1];" : "=f"(v) : "r"(addr));
    return v;
}
__device__ __forceinline__ void mma_tf32(float* d, const uint32_t* a, const uint32_t* b) {
    asm volatile(
        "mma.sync.aligned.m16n8k8.row.col.f32.tf32.tf32.f32 "
        "{%0,%1,%2,%3}, {%4,%5,%6,%7}, {%8,%9}, {%0,%1,%2,%3};\n"
        : "+f"(d[0]), "+f"(d[1]), "+f"(d[2]), "+f"(d[3])
        : "r"(a[0]), "r"(a[1]), "r"(a[2]), "r"(a[3]),
          "r"(b[0]), "r"(b[1]));
}

// ---------------- routing kernels ----------------
__global__ void init_kernel() {
    int i = threadIdx.x;
    if (i < NEXP) g_counts[i] = 0;
}

__global__ void gate_kernel(const float* __restrict__ x, const float* __restrict__ gumbel,
                            const float* __restrict__ gw, const float* __restrict__ gb) {
    int t = (blockIdx.x * blockDim.x + threadIdx.x) >> 5;
    int lane = threadIdx.x & 31;
    if (t >= T_TOK) return;
    const float* xr = x + (size_t)t * DMODEL;
    float acc[NEXP];
#pragma unroll
    for (int e = 0; e < NEXP; e++) acc[e] = 0.f;
    for (int d = lane * 4; d < DMODEL; d += 128) {
        float4 xv = *reinterpret_cast<const float4*>(xr + d);
        float xs[4] = {xv.x, xv.y, xv.z, xv.w};
        const float* g0 = gw + (size_t)d * NEXP;
#pragma unroll
        for (int j = 0; j < 4; j++)
#pragma unroll
            for (int e = 0; e < NEXP; e++) acc[e] += xs[j] * g0[j * NEXP + e];
    }
#pragma unroll
    for (int e = 0; e < NEXP; e++)
#pragma unroll
        for (int off = 16; off; off >>= 1)
            acc[e] += __shfl_xor_sync(0xffffffffu, acc[e], off);
    if (lane == 0) {
        float v[NEXP];
#pragma unroll
        for (int e = 0; e < NEXP; e++) v[e] = acc[e] + gb[e] + gumbel[t * NEXP + e];
        int b0 = 0; float m0 = v[0];
#pragma unroll
        for (int e = 1; e < NEXP; e++) if (v[e] > m0) { m0 = v[e]; b0 = e; }
        int b1 = -1; float m1 = -3.4e38f;
#pragma unroll
        for (int e = 0; e < NEXP; e++) {
            if (e == b0) continue;
            if (v[e] > m1) { m1 = v[e]; b1 = e; }
        }
        float e1v = expf(m1 - m0);
        float inv = 1.f / (1.f + e1v);
        g_e0[t] = b0; g_e1[t] = b1;
        g_w0[t] = inv; g_w1w[t] = e1v * inv;
        atomicAdd(&g_counts[b0], 1);
        atomicAdd(&g_counts[b1], 1);
    }
}

__global__ void scan_kernel() {
    if (threadIdx.x == 0) {
        int off = 0, nt = 0;
        for (int e = 0; e < NEXP; e++) {
            g_offsets[e] = off; g_fill[e] = 0;
            int c = g_counts[e];
            for (int s = 0; s < c; s += 128) {
                g_tile_e[nt] = e;
                g_tile_start[nt] = off + s;
                g_tile_cnt[nt] = (c - s < 128) ? (c - s) : 128;
                nt++;
            }
            off += c;
        }
        g_ntiles = nt;
    }
}

__global__ void scatter_kernel() {
    int t = blockIdx.x * blockDim.x + threadIdx.x;
    if (t >= T_TOK) return;
    int e0 = g_e0[t];
    int s0 = g_offsets[e0] + atomicAdd(&g_fill[e0], 1);
    g_tok[s0] = t; g_s0[t] = s0;
    int e1 = g_e1[t];
    int s1 = g_offsets[e1] + atomicAdd(&g_fill[e1], 1);
    g_tok[s1] = t; g_s1[t] = s1;
}

// ---------------- tf32-RNA elementwise pre-round ----------------
__global__ void rna_copy(const float* __restrict__ in, float* __restrict__ out, int n4) {
    int i = blockIdx.x * blockDim.x + threadIdx.x;
    if (i >= n4) return;
    float4 v = reinterpret_cast<const float4*>(in)[i];
    v.x = tf32r(v.x); v.y = tf32r(v.y); v.z = tf32r(v.z); v.w = tf32r(v.w);
    reinterpret_cast<float4*>(out)[i] = v;
}

// ---------------- grouped GEMM: mma.sync tf32, cp.async 3-stage, swizzled smem ----
// BM=128 BN=128 BK=32, 256 threads (8 warps, warp tile 32x64).
// Stage layout (32 KB each): A = 128 rows x 128B, byte(m,kg16) = m*128 + 16*(kg ^ (m&7))
//                            B = 32 rows x 512B,  byte(k,cg16) = k*512 + 16*(cg ^ (2*(k&3)))
#define STAGE_BYTES 32768
#define NSTAGE 3
#define SMEM_TOT (NSTAGE * STAGE_BYTES)

template <bool GATHER, bool RELU>
__global__ void __launch_bounds__(256, 2)
gemm_cp(const float* __restrict__ Aext, int lda,
        const float* __restrict__ B, long estride, int ldb,
        const float* __restrict__ bias, int ldo, int Ksize) {
    extern __shared__ char smem[];
    int bx = blockIdx.x;
    if (bx >= g_ntiles) return;
    int e = g_tile_e[bx];
    int slot0 = g_tile_start[bx];
    int mc = g_tile_cnt[bx];
    int n0 = blockIdx.y * 128;

    uint32_t sm = smem_u32(smem);
    int tid = threadIdx.x;
    int lane = tid & 31, wid = tid >> 5;
    int warpM = wid & 3, warpN = wid >> 2;
    int gid = lane >> 2, tig = lane & 3;

    const float* Abase = GATHER ? Aext : g_h;
    const float* Be = B + (size_t)e * estride;
    const float* biasE = bias + (size_t)e * ldo;

    // ---- staging maps (per thread: 4 x 16B for A, 4 x 16B for B) ----
    const float* aS[4]; uint32_t aD[4];
#pragma unroll
    for (int i = 0; i < 4; i++) {
        int f = i * 256 + tid;
        int row = f >> 3, kg = f & 7;
        aD[i] = (uint32_t)row * 128u + 16u * (uint32_t)(kg ^ (row & 7));
        int rc = row < mc ? row : (mc - 1);
        long arow = GATHER ? g_tok[slot0 + rc] : (slot0 + rc);
        aS[i] = Abase + (size_t)arow * lda + kg * 4;
    }
    const float* bS[4]; uint32_t bD[4];
#pragma unroll
    for (int i = 0; i < 4; i++) {
        int f = i * 256 + tid;
        int k = f >> 5, cg = f & 31;
        bD[i] = (uint32_t)k * 512u + 16u * (uint32_t)(cg ^ (2 * (k & 3)));
        bS[i] = Be + (size_t)k * ldb + n0 + cg * 4;
    }

    // ---- fragment address precompute ----
    uint32_t aoffv[8];
#pragma unroll
    for (int kg = 0; kg < 8; kg++) aoffv[kg] = 16u * (uint32_t)(kg ^ gid);
    uint32_t arel = (uint32_t)(warpM * 32 + gid) * 128u + (uint32_t)tig * 4u;
    uint32_t brel[8];
#pragma unroll
    for (int nt = 0; nt < 8; nt++) {
        uint32_t cg = (uint32_t)(warpN * 16 + nt * 2 + (gid >> 2));
        brel[nt] = (uint32_t)tig * 512u + 16u * (cg ^ (uint32_t)(2 * tig)) + (uint32_t)(gid & 3) * 4u;
    }

    float c[2][8][4];
#pragma unroll
    for (int mt = 0; mt < 2; mt++)
#pragma unroll
        for (int nt = 0; nt < 8; nt++)
#pragma unroll
            for (int q = 0; q < 4; q++) c[mt][nt][q] = 0.f;

    const int nk = Ksize / 32;

    // prologue: issue stages 0 and 1
#pragma unroll
    for (int s = 0; s < 2; s++) {
        uint32_t sb = sm + s * STAGE_BYTES;
#pragma unroll
        for (int i = 0; i < 4; i++) cp16(sb + aD[i], aS[i] + s * 32);
#pragma unroll
        for (int i = 0; i < 4; i++) cp16(sb + 16384u + bD[i], bS[i] + (size_t)s * 32 * ldb);
        cp_commit();
    }

    int stage = 0;
    for (int kc = 0; kc < nk; kc++) {
        cp_wait1();
        __syncthreads();
        // issue stage kc+2
        if (kc + 2 < nk) {
            int s2 = stage + 2; if (s2 >= NSTAGE) s2 -= NSTAGE;
            uint32_t sb = sm + (uint32_t)s2 * STAGE_BYTES;
            long ko = (long)(kc + 2) * 32;
#pragma unroll
            for (int i = 0; i < 4; i++) cp16(sb + aD[i], aS[i] + ko);
#pragma unroll
            for (int i = 0; i < 4; i++) cp16(sb + 16384u + bD[i], bS[i] + (size_t)(kc + 2) * 32 * ldb);
        }
        cp_commit();

        uint32_t aB = sm + (uint32_t)stage * STAGE_BYTES;
        uint32_t bB = aB + 16384u;
#pragma unroll
        for (int ks = 0; ks < 4; ks++) {
            uint32_t af[2][4];
#pragma unroll
            for (int mt = 0; mt < 2; mt++) {
                uint32_t a0 = aB + arel + (uint32_t)(mt * 2048) + aoffv[2 * ks];
                uint32_t a2 = aB + arel + (uint32_t)(mt * 2048) + aoffv[2 * ks + 1];
                af[mt][0] = __float_as_uint(lds(a0));
                af[mt][1] = __float_as_uint(lds(a0 + 1024u));
                af[mt][2] = __float_as_uint(lds(a2));
                af[mt][3] = __float_as_uint(lds(a2 + 1024u));
            }
            uint32_t bf[8][2];
#pragma unroll
            for (int nt = 0; nt < 8; nt++) {
                uint32_t b0 = bB + brel[nt] + (uint32_t)(ks * 4096);
                bf[nt][0] = __float_as_uint(lds(b0));
                bf[nt][1] = __float_as_uint(lds(b0 + 2048u));
            }
#pragma unroll
            for (int mt = 0; mt < 2; mt++)
#pragma unroll
                for (int nt = 0; nt < 8; nt++)
                    mma_tf32(c[mt][nt], af[mt], bf[nt]);
        }
        stage++; if (stage >= NSTAGE) stage -= NSTAGE;
    }

    // ---- epilogue: +bias (, relu + RNA), rows slot0+r ----
    float* Out = RELU ? g_h : g_y;
#pragma unroll
    for (int mt = 0; mt < 2; mt++) {
        int rb = warpM * 32 + mt * 16 + gid;
#pragma unroll
        for (int half = 0; half < 2; half++) {
            int r = rb + half * 8;
            if (r < mc) {
                float* orow = Out + (size_t)(slot0 + r) * ldo;
#pragma unroll
                for (int nt = 0; nt < 8; nt++) {
                    int nc = n0 + warpN * 64 + nt * 8 + 2 * tig;
                    float v0 = c[mt][nt][half * 2 + 0] + biasE[nc];
                    float v1 = c[mt][nt][half * 2 + 1] + biasE[nc + 1];
                    if (RELU) {
                        v0 = tf32r(fmaxf(v0, 0.f));
                        v1 = tf32r(fmaxf(v1, 0.f));
                    }
                    orow[nc]     = v0;
                    orow[nc + 1] = v1;
                }
            }
        }
    }
}

// ---------------- combine ----------------
__global__ void combine_kernel(float* __restrict__ out) {
    int idx = blockIdx.x * blockDim.x + threadIdx.x;
    if (idx >= T_TOK * (DMODEL / 4)) return;
    int t = idx / (DMODEL / 4);
    int j = (idx % (DMODEL / 4)) * 4;
    float w0 = g_w0[t], w1 = g_w1w[t];
    const float4 a = *reinterpret_cast<const float4*>(&g_y[(size_t)g_s0[t] * DMODEL + j]);
    const float4 b = *reinterpret_cast<const float4*>(&g_y[(size_t)g_s1[t] * DMODEL + j]);
    float4 o;
    o.x = w0 * a.x + w1 * b.x;
    o.y = w0 * a.y + w1 * b.y;
    o.z = w0 * a.z + w1 * b.z;
    o.w = w0 * a.w + w1 * b.w;
    *reinterpret_cast<float4*>(out + (size_t)t * DMODEL + j) = o;
}

// ---------------- launch ----------------
extern "C" void kernel_launch(void* const* d_in, const int* in_sizes, int n_in,
                              void* d_out, int out_size) {
    const float* x      = (const float*)d_in[0];
    const float* gumbel = (const float*)d_in[1];
    const float* gw     = (const float*)d_in[2];
    const float* gb     = (const float*)d_in[3];
    const float* w1     = (const float*)d_in[4];
    const float* b1     = (const float*)d_in[5];
    const float* w2     = (const float*)d_in[6];
    const float* b2     = (const float*)d_in[7];
    float* out = (float*)d_out;

    cudaFuncSetAttribute(gemm_cp<true, true>,
                         cudaFuncAttributeMaxDynamicSharedMemorySize, SMEM_TOT);
    cudaFuncSetAttribute(gemm_cp<false, false>,
                         cudaFuncAttributeMaxDynamicSharedMemorySize, SMEM_TOT);

    float* w1r; cudaGetSymbolAddress((void**)&w1r, g_w1r);
    float* w2r; cudaGetSymbolAddress((void**)&w2r, g_w2r);
    float* xr;  cudaGetSymbolAddress((void**)&xr,  g_xr);

    init_kernel<<<1, 32>>>();
    gate_kernel<<<T_TOK / 8, 256>>>(x, gumbel, gw, gb);
    scan_kernel<<<1, 1>>>();
    scatter_kernel<<<(T_TOK + 255) / 256, 256>>>();

    // RNA pre-rounding (cp.async can't convert; avoids tf32 truncation bias)
    {
        int n4 = T_TOK * DMODEL / 4;
        rna_copy<<<(n4 + 255) / 256, 256>>>(x, xr, n4);
        n4 = NEXP * DMODEL * DFF / 4;
        rna_copy<<<(n4 + 255) / 256, 256>>>(w1, w1r, n4);
        rna_copy<<<(n4 + 255) / 256, 256>>>(w2, w2r, n4);
    }

    // GEMM1: h = rna(relu(xr[tok] @ w1r[e] + b1[e]))   K=DMODEL, N=DFF
    gemm_cp<true, true><<<dim3(MAXTILES, DFF / 128), 256, SMEM_TOT>>>(
        xr, DMODEL, w1r, (long)DMODEL * DFF, DFF, b1, DFF, DMODEL);
    // GEMM2: y = h @ w2r[e] + b2[e]                    K=DFF, N=DMODEL
    gemm_cp<false, false><<<dim3(MAXTILES, DMODEL / 128), 256, SMEM_TOT>>>(
        nullptr, DFF, w2r, (long)DFF * DMODEL, DMODEL, b2, DMODEL, DFF);
    combine_kernel<<<(T_TOK * (DMODEL / 4) + 255) / 256, 256>>>(out);
}

// round 7
// speedup vs baseline: 2.5440x; 1.0420x over previous
#include <cuda_runtime.h>
#include <cstdint>

// ---------------- problem constants ----------------
#define T_TOK   8192
#define DMODEL  1024
#define DFF     4096
#define NEXP    8
#define ECAP    4096                 // fixed capacity per expert (mean 2048; 48-sigma headroom)
#define NSLOTS  (NEXP * ECAP)        // 32768
#define MAXTILES 160

// ---------------- device scratch (static; no allocation) ----------------
__device__ float g_h[(size_t)NSLOTS * DFF];            // 512 MiB
__device__ float g_y[(size_t)NSLOTS * DMODEL];         // 128 MiB
__device__ float g_w1r[(size_t)NEXP * DMODEL * DFF];   // RNA-rounded w1
__device__ float g_w2r[(size_t)NEXP * DFF * DMODEL];   // RNA-rounded w2
__device__ float g_xr[(size_t)T_TOK * DMODEL];         // RNA-rounded x
__device__ int   g_tok[NSLOTS];
__device__ int   g_s0[T_TOK], g_s1[T_TOK];
__device__ float g_w0[T_TOK], g_w1w[T_TOK];
__device__ int   g_fill[NEXP];
__device__ int   g_ntiles;
__device__ int   g_tile_e[MAXTILES], g_tile_start[MAXTILES], g_tile_cnt[MAXTILES];

// ---------------- helpers ----------------
__device__ __forceinline__ float tf32r(float x) {
    uint32_t u;
    asm("cvt.rna.tf32.f32 %0, %1;" : "=r"(u) : "f"(x));
    return __uint_as_float(u);
}
__device__ __forceinline__ uint32_t smem_u32(const void* p) {
    uint32_t a;
    asm("{ .reg .u64 t; cvta.to.shared.u64 t, %1; cvt.u32.u64 %0, t; }" : "=r"(a) : "l"(p));
    return a;
}
__device__ __forceinline__ void cp16(uint32_t dst, const void* src) {
    asm volatile("cp.async.cg.shared.global [%0], [%1], 16;" :: "r"(dst), "l"(src));
}
__device__ __forceinline__ void cp_commit() {
    asm volatile("cp.async.commit_group;" ::: "memory");
}
__device__ __forceinline__ void cp_wait1() {
    asm volatile("cp.async.wait_group 1;" ::: "memory");
}
__device__ __forceinline__ float lds(uint32_t addr) {
    float v;
    asm volatile("ld.shared.f32 %0, [%1];" : "=f"(v) : "r"(addr));
    return v;
}
__device__ __forceinline__ void mma_tf32(float* d, const uint32_t* a, const uint32_t* b) {
    asm volatile(
        "mma.sync.aligned.m16n8k8.row.col.f32.tf32.tf32.f32 "
        "{%0,%1,%2,%3}, {%4,%5,%6,%7}, {%8,%9}, {%0,%1,%2,%3};\n"
        : "+f"(d[0]), "+f"(d[1]), "+f"(d[2]), "+f"(d[3])
        : "r"(a[0]), "r"(a[1]), "r"(a[2]), "r"(a[3]),
          "r"(b[0]), "r"(b[1]));
}

// ---------------- launch 0: RNA-round both weight tensors (+ zero fill counters) ----
#define W_ELEMS4 ((size_t)NEXP * DMODEL * DFF / 4)     // float4 count per weight tensor
__global__ void rna_weights(const float* __restrict__ w1, const float* __restrict__ w2) {
    if (blockIdx.x == 0 && threadIdx.x < NEXP) g_fill[threadIdx.x] = 0;
    size_t i = (size_t)blockIdx.x * blockDim.x + threadIdx.x;
    if (i < W_ELEMS4) {
        float4 v = reinterpret_cast<const float4*>(w1)[i];
        v.x = tf32r(v.x); v.y = tf32r(v.y); v.z = tf32r(v.z); v.w = tf32r(v.w);
        reinterpret_cast<float4*>(g_w1r)[i] = v;
    } else if (i < 2 * W_ELEMS4) {
        size_t j = i - W_ELEMS4;
        float4 v = reinterpret_cast<const float4*>(w2)[j];
        v.x = tf32r(v.x); v.y = tf32r(v.y); v.z = tf32r(v.z); v.w = tf32r(v.w);
        reinterpret_cast<float4*>(g_w2r)[j] = v;
    }
}

// ---------------- launch 1: gate + RNA(x) + direct slot assignment ----------------
__global__ void gate_kernel(const float* __restrict__ x, const float* __restrict__ gumbel,
                            const float* __restrict__ gw, const float* __restrict__ gb) {
    int t = (blockIdx.x * blockDim.x + threadIdx.x) >> 5;
    int lane = threadIdx.x & 31;
    if (t >= T_TOK) return;
    const float* xr = x + (size_t)t * DMODEL;
    float* xo = g_xr + (size_t)t * DMODEL;
    float acc[NEXP];
#pragma unroll
    for (int e = 0; e < NEXP; e++) acc[e] = 0.f;
    for (int d = lane * 4; d < DMODEL; d += 128) {
        float4 xv = *reinterpret_cast<const float4*>(xr + d);
        // emit RNA-rounded copy of x (used as GEMM1 A operand)
        float4 rv;
        rv.x = tf32r(xv.x); rv.y = tf32r(xv.y); rv.z = tf32r(xv.z); rv.w = tf32r(xv.w);
        *reinterpret_cast<float4*>(xo + d) = rv;
        float xs[4] = {xv.x, xv.y, xv.z, xv.w};
        const float* g0 = gw + (size_t)d * NEXP;
#pragma unroll
        for (int j = 0; j < 4; j++)
#pragma unroll
            for (int e = 0; e < NEXP; e++) acc[e] += xs[j] * g0[j * NEXP + e];
    }
#pragma unroll
    for (int e = 0; e < NEXP; e++)
#pragma unroll
        for (int off = 16; off; off >>= 1)
            acc[e] += __shfl_xor_sync(0xffffffffu, acc[e], off);
    if (lane == 0) {
        float v[NEXP];
#pragma unroll
        for (int e = 0; e < NEXP; e++) v[e] = acc[e] + gb[e] + gumbel[t * NEXP + e];
        int b0 = 0; float m0 = v[0];
#pragma unroll
        for (int e = 1; e < NEXP; e++) if (v[e] > m0) { m0 = v[e]; b0 = e; }
        int b1 = -1; float m1 = -3.4e38f;
#pragma unroll
        for (int e = 0; e < NEXP; e++) {
            if (e == b0) continue;
            if (v[e] > m1) { m1 = v[e]; b1 = e; }
        }
        float e1v = expf(m1 - m0);
        float inv = 1.f / (1.f + e1v);
        g_w0[t] = inv; g_w1w[t] = e1v * inv;
        int s0 = b0 * ECAP + atomicAdd(&g_fill[b0], 1);
        g_tok[s0] = t; g_s0[t] = s0;
        int s1 = b1 * ECAP + atomicAdd(&g_fill[b1], 1);
        g_tok[s1] = t; g_s1[t] = s1;
    }
}

// ---------------- launch 2: build m-tile map ----------------
__global__ void tilemap_kernel() {
    if (threadIdx.x == 0) {
        int nt = 0;
        for (int e = 0; e < NEXP; e++) {
            int c = g_fill[e];
            if (c > ECAP) c = ECAP;
            int base = e * ECAP;
            for (int s = 0; s < c; s += 128) {
                g_tile_e[nt] = e;
                g_tile_start[nt] = base + s;
                g_tile_cnt[nt] = (c - s < 128) ? (c - s) : 128;
                nt++;
            }
        }
        g_ntiles = nt;
    }
}

// ---------------- grouped GEMM: BM=128 BN=128 BK=32, 4 warps, warp tile 64x64 ----
// cp.async 3-stage, swizzled smem (A: 128B rows, unit kg^(row&7); B: 512B rows,
// unit cg^(2*(k&3))). Warp grid 2x2 of 64x64 -> operand fragment reuse doubles,
// cutting smem crossbar traffic per chunk from 128KB to 96KB.
#define STAGE_BYTES 32768
#define NSTAGE 3
#define SM_TOKS (NSTAGE * STAGE_BYTES)          // 98304
#define SMEM_TOT (SM_TOKS + 512)

template <bool GATHER, bool RELU>
__global__ void __launch_bounds__(128, 2)
gemm_cp(const float* __restrict__ Aext, int lda,
        const float* __restrict__ B, long estride, int ldb,
        const float* __restrict__ bias, int ldo, int Ksize) {
    extern __shared__ char smem[];
    int bx = blockIdx.x;
    if (bx >= g_ntiles) return;
    int e = g_tile_e[bx];
    int slot0 = g_tile_start[bx];
    int mc = g_tile_cnt[bx];
    int n0 = blockIdx.y * 128;

    uint32_t sm = smem_u32(smem);
    int tid = threadIdx.x;
    int lane = tid & 31, wid = tid >> 5;
    int wm = wid >> 1, wn = wid & 1;          // 2x2 warps, 64x64 each
    int gid = lane >> 2, tig = lane & 3;

    const float* Abase = GATHER ? Aext : g_h;
    const float* biasE = bias + (size_t)e * ldo;

    // cache gathered token ids in smem (saves 8 x 64-bit pointer regs)
    int* toks = reinterpret_cast<int*>(smem + SM_TOKS);
    if (GATHER) {
        if (tid < 128) {
            int r = tid < mc ? tid : (mc - 1);
            toks[tid] = g_tok[slot0 + r];
        }
        __syncthreads();
    }

    // ---- staging constants (per thread: 8 x 16B for A, 8 x 16B for B) ----
    int r0 = tid >> 3, kg = tid & 7;                     // A: rows r0+16i, unit kg
    uint32_t aD0 = (uint32_t)r0 * 128u + 16u * (uint32_t)(kg ^ (r0 & 7));
    int bk0 = tid >> 5, bcg = tid & 31;                  // B: k rows bk0+4i, unit bcg
    uint32_t bD0 = (uint32_t)bk0 * 512u + 16u * (uint32_t)(bcg ^ (2 * (bk0 & 3)));

    uint32_t arow[8];                                    // A row offsets in elements
#pragma unroll
    for (int i = 0; i < 8; i++) {
        int row = i * 16 + r0;
        int rr = GATHER ? toks[row] : (slot0 + row);
        arow[i] = (uint32_t)rr * (uint32_t)lda;
    }
    const float* Ab = Abase + kg * 4;
    const float* Bp = B + (size_t)e * estride + (size_t)bk0 * ldb + n0 + bcg * 4;

    // ---- fragment addressing ----
    uint32_t arel = (uint32_t)(wm * 64 + gid) * 128u + (uint32_t)tig * 4u;
    uint32_t aoffv[8];
#pragma unroll
    for (int u = 0; u < 8; u++) aoffv[u] = 16u * (uint32_t)(u ^ gid);
    uint32_t brel[8];
#pragma unroll
    for (int nt = 0; nt < 8; nt++) {
        uint32_t cg = (uint32_t)(wn * 16 + nt * 2 + (gid >> 2));
        brel[nt] = (uint32_t)tig * 512u + 16u * (cg ^ (uint32_t)(2 * tig)) + (uint32_t)(gid & 3) * 4u;
    }

    float c[4][8][4];
#pragma unroll
    for (int mt = 0; mt < 4; mt++)
#pragma unroll
        for (int nt = 0; nt < 8; nt++)
#pragma unroll
            for (int q = 0; q < 4; q++) c[mt][nt][q] = 0.f;

    const int nk = Ksize / 32;

    // prologue: stages 0 and 1
#pragma unroll
    for (int s = 0; s < 2; s++) {
        uint32_t sb = sm + (uint32_t)s * STAGE_BYTES;
#pragma unroll
        for (int i = 0; i < 8; i++) cp16(sb + aD0 + (uint32_t)i * 2048u, Ab + arow[i] + s * 32);
#pragma unroll
        for (int i = 0; i < 8; i++) cp16(sb + 16384u + bD0 + (uint32_t)i * 2048u,
                                         Bp + (size_t)(s * 32 + i * 4) * ldb);
        cp_commit();
    }

    int stage = 0;
    for (int kc = 0; kc < nk; kc++) {
        cp_wait1();
        __syncthreads();
        if (kc + 2 < nk) {
            int s2 = stage + 2; if (s2 >= NSTAGE) s2 -= NSTAGE;
            uint32_t sb = sm + (uint32_t)s2 * STAGE_BYTES;
            int ko = (kc + 2) * 32;
#pragma unroll
            for (int i = 0; i < 8; i++) cp16(sb + aD0 + (uint32_t)i * 2048u, Ab + arow[i] + ko);
#pragma unroll
            for (int i = 0; i < 8; i++) cp16(sb + 16384u + bD0 + (uint32_t)i * 2048u,
                                             Bp + (size_t)(ko + i * 4) * ldb);
        }
        cp_commit();

        uint32_t aB = sm + (uint32_t)stage * STAGE_BYTES;
        uint32_t bB = aB + 16384u;
#pragma unroll
        for (int ks = 0; ks < 4; ks++) {
            uint32_t af[4][4];
#pragma unroll
            for (int mt = 0; mt < 4; mt++) {
                uint32_t base = aB + arel + (uint32_t)(mt * 2048);
                uint32_t a0 = base + aoffv[2 * ks];
                uint32_t a2 = base + aoffv[2 * ks + 1];
                af[mt][0] = __float_as_uint(lds(a0));
                af[mt][1] = __float_as_uint(lds(a0 + 1024u));
                af[mt][2] = __float_as_uint(lds(a2));
                af[mt][3] = __float_as_uint(lds(a2 + 1024u));
            }
            uint32_t bf[8][2];
#pragma unroll
            for (int nt = 0; nt < 8; nt++) {
                uint32_t b0 = bB + brel[nt] + (uint32_t)(ks * 4096);
                bf[nt][0] = __float_as_uint(lds(b0));
                bf[nt][1] = __float_as_uint(lds(b0 + 2048u));
            }
#pragma unroll
            for (int mt = 0; mt < 4; mt++)
#pragma unroll
                for (int nt = 0; nt < 8; nt++)
                    mma_tf32(c[mt][nt], af[mt], bf[nt]);
        }
        stage++; if (stage >= NSTAGE) stage -= NSTAGE;
    }

    // ---- epilogue: +bias (, relu + RNA) ----
    float* Out = RELU ? g_h : g_y;
#pragma unroll
    for (int mt = 0; mt < 4; mt++) {
#pragma unroll
        for (int half = 0; half < 2; half++) {
            int r = wm * 64 + mt * 16 + gid + half * 8;
            if (r < mc) {
                float* orow = Out + (size_t)(slot0 + r) * ldo;
#pragma unroll
                for (int nt = 0; nt < 8; nt++) {
                    int nc = n0 + wn * 64 + nt * 8 + 2 * tig;
                    float v0 = c[mt][nt][half * 2 + 0] + biasE[nc];
                    float v1 = c[mt][nt][half * 2 + 1] + biasE[nc + 1];
                    if (RELU) {
                        v0 = tf32r(fmaxf(v0, 0.f));
                        v1 = tf32r(fmaxf(v1, 0.f));
                    }
                    orow[nc]     = v0;
                    orow[nc + 1] = v1;
                }
            }
        }
    }
}

// ---------------- combine ----------------
__global__ void combine_kernel(float* __restrict__ out) {
    int idx = blockIdx.x * blockDim.x + threadIdx.x;
    if (idx >= T_TOK * (DMODEL / 4)) return;
    int t = idx / (DMODEL / 4);
    int j = (idx % (DMODEL / 4)) * 4;
    float w0 = g_w0[t], w1 = g_w1w[t];
    const float4 a = *reinterpret_cast<const float4*>(&g_y[(size_t)g_s0[t] * DMODEL + j]);
    const float4 b = *reinterpret_cast<const float4*>(&g_y[(size_t)g_s1[t] * DMODEL + j]);
    float4 o;
    o.x = w0 * a.x + w1 * b.x;
    o.y = w0 * a.y + w1 * b.y;
    o.z = w0 * a.z + w1 * b.z;
    o.w = w0 * a.w + w1 * b.w;
    *reinterpret_cast<float4*>(out + (size_t)t * DMODEL + j) = o;
}

// ---------------- launch (order matters: ncu captures launch index 3 = GEMM1) ----
extern "C" void kernel_launch(void* const* d_in, const int* in_sizes, int n_in,
                              void* d_out, int out_size) {
    const float* x      = (const float*)d_in[0];
    const float* gumbel = (const float*)d_in[1];
    const float* gw     = (const float*)d_in[2];
    const float* gb     = (const float*)d_in[3];
    const float* w1     = (const float*)d_in[4];
    const float* b1     = (const float*)d_in[5];
    const float* w2     = (const float*)d_in[6];
    const float* b2     = (const float*)d_in[7];
    float* out = (float*)d_out;

    cudaFuncSetAttribute(gemm_cp<true, true>,
                         cudaFuncAttributeMaxDynamicSharedMemorySize, SMEM_TOT);
    cudaFuncSetAttribute(gemm_cp<false, false>,
                         cudaFuncAttributeMaxDynamicSharedMemorySize, SMEM_TOT);

    float* xr;  cudaGetSymbolAddress((void**)&xr,  g_xr);
    float* w1r; cudaGetSymbolAddress((void**)&w1r, g_w1r);
    float* w2r; cudaGetSymbolAddress((void**)&w2r, g_w2r);

    // 0: weight RNA + counter zeroing
    size_t n4 = 2 * W_ELEMS4;
    rna_weights<<<(unsigned)((n4 + 255) / 256), 256>>>(w1, w2);
    // 1: gate (logits, top-2, slot assignment, RNA(x))
    gate_kernel<<<T_TOK * 32 / 256, 256>>>(x, gumbel, gw, gb);
    // 2: tile map
    tilemap_kernel<<<1, 32>>>();
    // 3: GEMM1  h = rna(relu(xr[tok] @ w1r[e] + b1[e]))   K=DMODEL, N=DFF
    gemm_cp<true, true><<<dim3(MAXTILES, DFF / 128), 128, SMEM_TOT>>>(
        xr, DMODEL, w1r, (long)DMODEL * DFF, DFF, b1, DFF, DMODEL);
    // 4: GEMM2  y = h @ w2r[e] + b2[e]                    K=DFF, N=DMODEL
    gemm_cp<false, false><<<dim3(MAXTILES, DMODEL / 128), 128, SMEM_TOT>>>(
        nullptr, DFF, w2r, (long)DFF * DMODEL, DMODEL, b2, DMODEL, DFF);
    // 5: combine
    combine_kernel<<<(T_TOK * (DMODEL / 4) + 255) / 256, 256>>>(out);
}